// round 8
// baseline (speedup 1.0000x reference)
#include <cuda_runtime.h>
#include <cuda_bf16.h>
#include <math.h>
#include <stdint.h>

#define K_DIM 2144     // 64 + 2016 + 64
#define M_ROWS 20000   // 400 sequences * 50 segments
#define M_PAD 20096    // 157 * 128
#define NSEG 50
#define GATES 512

// Scratch (device globals: allocation-free, zero-initialized .bss).
__device__ __nv_bfloat16 g_Ahi[(size_t)M_PAD * K_DIM];  // logsig features hi
__device__ __nv_bfloat16 g_Alo[(size_t)M_PAD * K_DIM];  // logsig features lo
__device__ __nv_bfloat16 g_Bhi[(size_t)GATES * K_DIM];  // W_ih hi
__device__ __nv_bfloat16 g_Blo[(size_t)GATES * K_DIM];  // W_ih lo
__device__ float g_xproj[(size_t)M_PAD * GATES];        // seq @ W_ih^T + b_ih + b_hh

__device__ __forceinline__ void split_bf16(float x, __nv_bfloat16& hi, __nv_bfloat16& lo) {
    hi = __float2bfloat16_rn(x);
    lo = __float2bfloat16_rn(x - __bfloat162float(hi));
}

// ---------------------------------------------------------------------------
// Kernel 1: segment log-signature -> split-bf16 feature rows.
// grid (50, 16, 5): z splits the 25 v values into chunks of 5.
// ---------------------------------------------------------------------------
__global__ void logsig_kernel(const float* __restrict__ x) {
    const int s  = blockIdx.x;       // 0..49
    const int b  = blockIdx.y;       // 0..15
    const int v0 = blockIdx.z * 5;   // 0,5,10,15,20
    __shared__ float sa[64 * 5];
    __shared__ float sb[64 * 5];
    __shared__ float sc[64 * 5];
    const int tid = threadIdx.x;

    // Phase 1: increments for this block's 5 v values (+ lvl1/start rows).
    for (int item = tid; item < 64 * 5; item += 256) {
        const int c  = item / 5;
        const int dv = item % 5;
        const int v  = v0 + dv;
        const long base = ((long)(b * 64 + c) * 200 + 4 * s) * 25 + v;
        const float p0 = x[base];
        const float p1 = x[base + 25];
        const float p2 = x[base + 50];
        const float p3 = x[base + 75];
        sa[c * 5 + dv] = p1 - p0;
        sb[c * 5 + dv] = p2 - p1;
        sc[c * 5 + dv] = p3 - p2;
        const size_t m = (size_t)(b * 25 + v) * NSEG + s;
        split_bf16(p3 - p0, g_Ahi[m * K_DIM + c],        g_Alo[m * K_DIM + c]);
        split_bf16(p0,      g_Ahi[m * K_DIM + 2080 + c], g_Alo[m * K_DIM + 2080 + c]);
    }
    __syncthreads();

    // Triangular (i,j) indices for this thread's 8 strided k values (once).
    int ii[8], jj[8];
    {
        int i = 0, off = 0;  // row i starts at off = 63*i - i*(i-1)/2
        for (int u = 0; u < 8; ++u) {
            const int k = tid + (u << 8);
            if (k < 2016) {
                while (off + (63 - i) <= k) { off += 63 - i; ++i; }
                ii[u] = i; jj[u] = i + 1 + (k - off);
            } else { ii[u] = 0; jj[u] = 1; }
        }
    }

    for (int dv = 0; dv < 5; ++dv) {
        const int v = v0 + dv;
        const size_t m = (size_t)(b * 25 + v) * NSEG + s;
        __nv_bfloat16* __restrict__ dh = g_Ahi + m * K_DIM + 64;
        __nv_bfloat16* __restrict__ dl = g_Alo + m * K_DIM + 64;
#pragma unroll
        for (int u = 0; u < 8; ++u) {
            const int k = tid + (u << 8);
            if (k < 2016) {
                const int i = ii[u], j = jj[u];
                const float ai = sa[i * 5 + dv], aj = sa[j * 5 + dv];
                const float bi = sb[i * 5 + dv], bj = sb[j * 5 + dv];
                const float ci = sc[i * 5 + dv], cj = sc[j * 5 + dv];
                const float val = 0.5f * (ai * bj - aj * bi + (ai + bi) * cj - (aj + bj) * ci);
                split_bf16(val, dh[k], dl[k]);
            }
        }
    }
}

// ---------------------------------------------------------------------------
// Kernel 1b: split W_ih into bf16 hi/lo.
// ---------------------------------------------------------------------------
__global__ void wconv_kernel(const float* __restrict__ W) {
    const int idx = blockIdx.x * 256 + threadIdx.x;
    if (idx < GATES * K_DIM) {
        split_bf16(W[idx], g_Bhi[idx], g_Blo[idx]);
    }
}

// ---------------------------------------------------------------------------
// Kernel 2: x_proj = seq @ W_ih^T + bias via split-bf16 HMMA (unchanged R6).
// ---------------------------------------------------------------------------
__device__ __forceinline__ void cp16(void* dst, const void* src) {
    const uint32_t d = (uint32_t)__cvta_generic_to_shared(dst);
    asm volatile("cp.async.cg.shared.global [%0], [%1], 16;\n" :: "r"(d), "l"(src));
}
__device__ __forceinline__ void ldsm4(uint32_t* r, const __nv_bfloat16* p) {
    const uint32_t a = (uint32_t)__cvta_generic_to_shared(p);
    asm volatile("ldmatrix.sync.aligned.m8n8.x4.shared.b16 {%0,%1,%2,%3}, [%4];"
                 : "=r"(r[0]), "=r"(r[1]), "=r"(r[2]), "=r"(r[3]) : "r"(a));
}
__device__ __forceinline__ void mma16816(float* c, const uint32_t* a, uint32_t b0, uint32_t b1) {
    asm volatile("mma.sync.aligned.m16n8k16.row.col.f32.bf16.bf16.f32 "
                 "{%0,%1,%2,%3}, {%4,%5,%6,%7}, {%8,%9}, {%0,%1,%2,%3};"
                 : "+f"(c[0]), "+f"(c[1]), "+f"(c[2]), "+f"(c[3])
                 : "r"(a[0]), "r"(a[1]), "r"(a[2]), "r"(a[3]), "r"(b0), "r"(b1));
}

#define NIT (K_DIM / 16)   // 134

__global__ __launch_bounds__(256, 1) void gemm_kernel(
    const float* __restrict__ b_ih,
    const float* __restrict__ b_hh)
{
    __shared__ __align__(128) __nv_bfloat16 sA[3][2][128 * 16];
    __shared__ __align__(128) __nv_bfloat16 sB[3][2][128 * 16];

    const int tid = threadIdx.x;
    const int bn = blockIdx.x * 128;   // n fastest -> A-tile L2 reuse
    const int bm = blockIdx.y * 128;

    const int prow = tid >> 1;
    const int pch  = tid & 1;
    const int psc  = pch ^ ((prow >> 2) & 1);
    const int psoff = prow * 16 + psc * 8;
    const size_t aoff = (size_t)(bm + prow) * K_DIM + pch * 8;
    const size_t boff = (size_t)(bn + prow) * K_DIM + pch * 8;

    const int lane = tid & 31;
    const int warp = tid >> 5;
    const int wm = warp >> 1;
    const int wn = warp & 1;
    int aoffs[2];
#pragma unroll
    for (int mf = 0; mf < 2; ++mf) {
        const int r = wm * 32 + mf * 16 + (lane & 15);
        const int c = lane >> 4;
        aoffs[mf] = r * 16 + (c ^ ((r >> 2) & 1)) * 8;
    }
    int boffs[4];
#pragma unroll
    for (int ng = 0; ng < 4; ++ng) {
        const int r = wn * 64 + ng * 16 + ((lane & 7) | ((lane >> 4) << 3));
        const int c = (lane >> 3) & 1;
        boffs[ng] = r * 16 + (c ^ ((r >> 2) & 1)) * 8;
    }

    float acc[2][8][4];
#pragma unroll
    for (int mf = 0; mf < 2; ++mf)
#pragma unroll
        for (int n8 = 0; n8 < 8; ++n8)
#pragma unroll
            for (int q = 0; q < 4; ++q) acc[mf][n8][q] = 0.f;

#pragma unroll
    for (int p = 0; p < 2; ++p) {
        const size_t kk = (size_t)p * 16;
        cp16(&sA[p][0][psoff], g_Ahi + aoff + kk);
        cp16(&sA[p][1][psoff], g_Alo + aoff + kk);
        cp16(&sB[p][0][psoff], g_Bhi + boff + kk);
        cp16(&sB[p][1][psoff], g_Blo + boff + kk);
        asm volatile("cp.async.commit_group;\n" ::);
    }

    int st = 0;
    for (int it = 0; it < NIT; ++it) {
        asm volatile("cp.async.wait_group 1;\n" ::);
        __syncthreads();

        if (it + 2 < NIT) {
            const int ns = (st + 2 >= 3) ? st - 1 : st + 2;
            const size_t kk = (size_t)(it + 2) * 16;
            cp16(&sA[ns][0][psoff], g_Ahi + aoff + kk);
            cp16(&sA[ns][1][psoff], g_Alo + aoff + kk);
            cp16(&sB[ns][0][psoff], g_Bhi + boff + kk);
            cp16(&sB[ns][1][psoff], g_Blo + boff + kk);
        }
        asm volatile("cp.async.commit_group;\n" ::);

        uint32_t ahi[2][4], alo[2][4], bhi[4][4], blo[4][4];
#pragma unroll
        for (int mf = 0; mf < 2; ++mf) {
            ldsm4(ahi[mf], &sA[st][0][aoffs[mf]]);
            ldsm4(alo[mf], &sA[st][1][aoffs[mf]]);
        }
#pragma unroll
        for (int ng = 0; ng < 4; ++ng) {
            ldsm4(bhi[ng], &sB[st][0][boffs[ng]]);
            ldsm4(blo[ng], &sB[st][1][boffs[ng]]);
        }
#pragma unroll
        for (int mf = 0; mf < 2; ++mf)
#pragma unroll
            for (int ng = 0; ng < 4; ++ng)
#pragma unroll
                for (int h = 0; h < 2; ++h) {
                    float* c = acc[mf][ng * 2 + h];
                    mma16816(c, ahi[mf], bhi[ng][2 * h], bhi[ng][2 * h + 1]);
                    mma16816(c, ahi[mf], blo[ng][2 * h], blo[ng][2 * h + 1]);
                    mma16816(c, alo[mf], bhi[ng][2 * h], bhi[ng][2 * h + 1]);
                }
        __syncthreads();
        st = (st == 2) ? 0 : st + 1;
    }

    const int qr = lane >> 2;
    const int qc = (lane & 3) * 2;
#pragma unroll
    for (int mf = 0; mf < 2; ++mf) {
#pragma unroll
        for (int n8 = 0; n8 < 8; ++n8) {
            const int m0 = bm + wm * 32 + mf * 16 + qr;
            const int n0 = bn + wn * 64 + n8 * 8 + qc;
            const float bias0 = b_ih[n0] + b_hh[n0];
            const float bias1 = b_ih[n0 + 1] + b_hh[n0 + 1];
            const float* c = acc[mf][n8];
            g_xproj[(size_t)m0 * GATES + n0]           = c[0] + bias0;
            g_xproj[(size_t)m0 * GATES + n0 + 1]       = c[1] + bias1;
            g_xproj[(size_t)(m0 + 8) * GATES + n0]     = c[2] + bias0;
            g_xproj[(size_t)(m0 + 8) * GATES + n0 + 1] = c[3] + bias1;
        }
    }
}

// ---------------------------------------------------------------------------
// Kernel 3: LSTM recurrence with packed fma.rn.f32x2 (Blackwell FFMA2).
// 148 blocks: 104 x 3 seqs + 44 x 2 seqs. Gate dot products use packed
// f32x2 FMAs: h pairs come pre-packed from ld.shared.v2.u64, lower-half
// W_hh packed into b64 regs once, upper-half via ld.global.nc.v2.u64.
// Halves the FFMA issue count (the measured bottleneck: rt_SMSP=2).
// ---------------------------------------------------------------------------
typedef unsigned long long u64t;

__device__ __forceinline__ void fma2(u64t& acc, u64t w, u64t h) {
    asm volatile("fma.rn.f32x2 %0, %1, %2, %0;" : "+l"(acc) : "l"(w), "l"(h));
}
__device__ __forceinline__ void lds2(u64t& a, u64t& b, uint32_t saddr) {
    asm volatile("ld.shared.v2.u64 {%0,%1}, [%2];" : "=l"(a), "=l"(b) : "r"(saddr));
}
__device__ __forceinline__ void ldg2(u64t& a, u64t& b, const float* p) {
    asm volatile("ld.global.nc.v2.u64 {%0,%1}, [%2];" : "=l"(a), "=l"(b) : "l"(p));
}
__device__ __forceinline__ u64t pack2(float lo, float hi) {
    u64t r;
    asm("mov.b64 %0, {%1,%2};" : "=l"(r) : "f"(lo), "f"(hi));
    return r;
}
__device__ __forceinline__ float redu2(u64t a, u64t b) {
    u64t s;
    asm("add.rn.f32x2 %0, %1, %2;" : "=l"(s) : "l"(a), "l"(b));
    float lo, hi;
    asm("mov.b64 {%0,%1}, %2;" : "=f"(lo), "=f"(hi) : "l"(s));
    return lo + hi;
}

__device__ __forceinline__ float fsig(float x) {
    const float z = __expf(-fabsf(x));
    const float p = __fdividef(1.f, 1.f + z);
    return x >= 0.f ? p : 1.f - p;
}
__device__ __forceinline__ float ftanh_(float x) {
    const float t = __expf(-2.f * fabsf(x));
    const float r = __fdividef(1.f - t, 1.f + t);
    return x >= 0.f ? r : -r;
}

__global__ __launch_bounds__(512, 1) void lstm_kernel(
    const float* __restrict__ Whh,
    float* __restrict__ out)
{
    __shared__ float h_sh[3 * 128];
    __shared__ float gates_sh[3 * 512];

    const int tid = threadIdx.x;
    const int blk = blockIdx.x;
    int n0, ns;
    if (blk < 104) { n0 = 3 * blk; ns = 3; }
    else           { n0 = 312 + 2 * (blk - 104); ns = 2; }

    // Lower 64 recurrent weights of this gate row, packed as 32 x f32x2.
    u64t wp[32];
    {
        const float4* wrow = (const float4*)(Whh + tid * 128);
#pragma unroll
        for (int i = 0; i < 16; i++) {
            const float4 t = wrow[i];
            wp[2 * i]     = pack2(t.x, t.y);
            wp[2 * i + 1] = pack2(t.z, t.w);
        }
    }
    const float* __restrict__ wgu = Whh + tid * 128 + 64;  // upper half (L1-hot)

    if (tid < 384) h_sh[tid] = 0.f;
    const int sq = tid >> 7;           // 0..3
    const int j  = tid & 127;
    const int active = (sq < ns);
    float creg = 0.f;
    const int n_pw = n0 + (active ? sq : 0);
    const int bb = n_pw / 25;
    const int vv = n_pw % 25;
    const long outbase = ((long)(bb * 128 + j) * 50) * 25 + vv;

    const uint32_t hs0 = (uint32_t)__cvta_generic_to_shared(&h_sh[0]);
    const uint32_t hs1 = (uint32_t)__cvta_generic_to_shared(&h_sh[128]);
    const uint32_t hs2 = (uint32_t)__cvta_generic_to_shared(&h_sh[256]);

    // prefetch step 0
    float xp0 = g_xproj[(size_t)((n0 + 0) * 50 + 0) * GATES + tid];
    float xp1 = g_xproj[(size_t)((n0 + 1) * 50 + 0) * GATES + tid];
    float xp2 = (ns == 3) ? g_xproj[(size_t)((n0 + 2) * 50 + 0) * GATES + tid] : 0.f;
    __syncthreads();

    for (int s = 0; s < NSEG; s++) {
        // prefetch next step's xproj
        float nx0 = 0.f, nx1 = 0.f, nx2 = 0.f;
        if (s + 1 < NSEG) {
            nx0 = g_xproj[(size_t)((n0 + 0) * 50 + s + 1) * GATES + tid];
            nx1 = g_xproj[(size_t)((n0 + 1) * 50 + s + 1) * GATES + tid];
            if (ns == 3) nx2 = g_xproj[(size_t)((n0 + 2) * 50 + s + 1) * GATES + tid];
        }

        // two accumulators per sequence (even/odd pairs) to relax the chain
        u64t a0 = pack2(xp0, 0.f), b0 = pack2(0.f, 0.f);
        u64t a1 = pack2(xp1, 0.f), b1 = pack2(0.f, 0.f);
        u64t a2 = pack2(xp2, 0.f), b2 = pack2(0.f, 0.f);

        // lower 64 k: weights in packed regs, h pairs via ld.shared.v2.u64
#pragma unroll
        for (int i = 0; i < 16; i++) {
            u64t h01, h23;
            lds2(h01, h23, hs0 + i * 16);
            fma2(a0, wp[2 * i], h01); fma2(b0, wp[2 * i + 1], h23);
            lds2(h01, h23, hs1 + i * 16);
            fma2(a1, wp[2 * i], h01); fma2(b1, wp[2 * i + 1], h23);
            lds2(h01, h23, hs2 + i * 16);
            fma2(a2, wp[2 * i], h01); fma2(b2, wp[2 * i + 1], h23);
        }
        // upper 64 k: weights via ld.global.nc.v2.u64 (L1-resident)
#pragma unroll
        for (int i = 0; i < 16; i++) {
            u64t w01, w23, h01, h23;
            ldg2(w01, w23, wgu + i * 4);
            lds2(h01, h23, hs0 + 256 + i * 16);
            fma2(a0, w01, h01); fma2(b0, w23, h23);
            lds2(h01, h23, hs1 + 256 + i * 16);
            fma2(a1, w01, h01); fma2(b1, w23, h23);
            lds2(h01, h23, hs2 + 256 + i * 16);
            fma2(a2, w01, h01); fma2(b2, w23, h23);
        }
        gates_sh[0 * 512 + tid] = redu2(a0, b0);
        gates_sh[1 * 512 + tid] = redu2(a1, b1);
        gates_sh[2 * 512 + tid] = redu2(a2, b2);
        __syncthreads();

        // pointwise: gates layout [i | f | g | o], 128 each
        if (active) {
            const float gi = gates_sh[sq * 512 + j];
            const float gf = gates_sh[sq * 512 + 128 + j];
            const float gg = gates_sh[sq * 512 + 256 + j];
            const float go = gates_sh[sq * 512 + 384 + j];
            creg = fsig(gf) * creg + fsig(gi) * ftanh_(gg);
            const float h = fsig(go) * ftanh_(creg);
            h_sh[sq * 128 + j] = h;
            out[outbase + (long)s * 25] = h;   // out[b, j, s, v]
        }
        __syncthreads();
        xp0 = nx0; xp1 = nx1; xp2 = nx2;
    }
}

// ---------------------------------------------------------------------------
extern "C" void kernel_launch(void* const* d_in, const int* in_sizes, int n_in,
                              void* d_out, int out_size) {
    const float* x    = (const float*)d_in[0];  // (16,64,200,25)
    const float* W_ih = (const float*)d_in[1];  // (512,2144)
    const float* W_hh = (const float*)d_in[2];  // (512,128)
    const float* b_ih = (const float*)d_in[3];  // (512)
    const float* b_hh = (const float*)d_in[4];  // (512)
    float* out = (float*)d_out;                 // (16,128,50,25)
    (void)in_sizes; (void)n_in; (void)out_size;

    dim3 gl(NSEG, 16, 5);
    logsig_kernel<<<gl, 256, 0, 0>>>(x);

    wconv_kernel<<<(GATES * K_DIM + 255) / 256, 256, 0, 0>>>(W_ih);

    dim3 gg(GATES / 128, M_PAD / 128);          // (4, 157): n fastest
    gemm_kernel<<<gg, 256, 0, 0>>>(b_ih, b_hh);

    lstm_kernel<<<148, 512, 0, 0>>>(W_hh, out);
}

// round 10
// speedup vs baseline: 1.1454x; 1.1454x over previous
#include <cuda_runtime.h>
#include <cuda_bf16.h>
#include <math.h>
#include <stdint.h>

#define K_DIM 2144     // 64 + 2016 + 64
#define M_ROWS 20000   // 400 sequences * 50 segments
#define M_PAD 20096    // 157 * 128
#define NSEG 50
#define GATES 512

// Scratch (device globals: allocation-free, zero-initialized .bss).
__device__ __nv_bfloat16 g_Ahi[(size_t)M_PAD * K_DIM];  // logsig features hi
__device__ __nv_bfloat16 g_Alo[(size_t)M_PAD * K_DIM];  // logsig features lo
__device__ __nv_bfloat16 g_Bhi[(size_t)GATES * K_DIM];  // W_ih hi
__device__ __nv_bfloat16 g_Blo[(size_t)GATES * K_DIM];  // W_ih lo
__device__ float g_xproj[(size_t)M_PAD * GATES];        // seq @ W_ih^T + b_ih + b_hh

__device__ __forceinline__ void split_bf16(float x, __nv_bfloat16& hi, __nv_bfloat16& lo) {
    hi = __float2bfloat16_rn(x);
    lo = __float2bfloat16_rn(x - __bfloat162float(hi));
}

// ---------------------------------------------------------------------------
// Kernel 1: segment log-signature -> split-bf16 feature rows.
// grid (50, 16, 5): z splits the 25 v values into chunks of 5.
// ---------------------------------------------------------------------------
__global__ void logsig_kernel(const float* __restrict__ x) {
    const int s  = blockIdx.x;       // 0..49
    const int b  = blockIdx.y;       // 0..15
    const int v0 = blockIdx.z * 5;   // 0,5,10,15,20
    __shared__ float sa[64 * 5];
    __shared__ float sb[64 * 5];
    __shared__ float sc[64 * 5];
    const int tid = threadIdx.x;

    // Phase 1: increments for this block's 5 v values (+ lvl1/start rows).
    for (int item = tid; item < 64 * 5; item += 256) {
        const int c  = item / 5;
        const int dv = item % 5;
        const int v  = v0 + dv;
        const long base = ((long)(b * 64 + c) * 200 + 4 * s) * 25 + v;
        const float p0 = x[base];
        const float p1 = x[base + 25];
        const float p2 = x[base + 50];
        const float p3 = x[base + 75];
        sa[c * 5 + dv] = p1 - p0;
        sb[c * 5 + dv] = p2 - p1;
        sc[c * 5 + dv] = p3 - p2;
        const size_t m = (size_t)(b * 25 + v) * NSEG + s;
        split_bf16(p3 - p0, g_Ahi[m * K_DIM + c],        g_Alo[m * K_DIM + c]);
        split_bf16(p0,      g_Ahi[m * K_DIM + 2080 + c], g_Alo[m * K_DIM + 2080 + c]);
    }
    __syncthreads();

    // Triangular (i,j) indices for this thread's 8 strided k values (once).
    int ii[8], jj[8];
    {
        int i = 0, off = 0;  // row i starts at off = 63*i - i*(i-1)/2
        for (int u = 0; u < 8; ++u) {
            const int k = tid + (u << 8);
            if (k < 2016) {
                while (off + (63 - i) <= k) { off += 63 - i; ++i; }
                ii[u] = i; jj[u] = i + 1 + (k - off);
            } else { ii[u] = 0; jj[u] = 1; }
        }
    }

    for (int dv = 0; dv < 5; ++dv) {
        const int v = v0 + dv;
        const size_t m = (size_t)(b * 25 + v) * NSEG + s;
        __nv_bfloat16* __restrict__ dh = g_Ahi + m * K_DIM + 64;
        __nv_bfloat16* __restrict__ dl = g_Alo + m * K_DIM + 64;
#pragma unroll
        for (int u = 0; u < 8; ++u) {
            const int k = tid + (u << 8);
            if (k < 2016) {
                const int i = ii[u], j = jj[u];
                const float ai = sa[i * 5 + dv], aj = sa[j * 5 + dv];
                const float bi = sb[i * 5 + dv], bj = sb[j * 5 + dv];
                const float ci = sc[i * 5 + dv], cj = sc[j * 5 + dv];
                const float val = 0.5f * (ai * bj - aj * bi + (ai + bi) * cj - (aj + bj) * ci);
                split_bf16(val, dh[k], dl[k]);
            }
        }
    }
}

// ---------------------------------------------------------------------------
// Kernel 1b: split W_ih into bf16 hi/lo.
// ---------------------------------------------------------------------------
__global__ void wconv_kernel(const float* __restrict__ W) {
    const int idx = blockIdx.x * 256 + threadIdx.x;
    if (idx < GATES * K_DIM) {
        split_bf16(W[idx], g_Bhi[idx], g_Blo[idx]);
    }
}

// ---------------------------------------------------------------------------
// Kernel 2: x_proj = seq @ W_ih^T + bias via split-bf16 HMMA.
// acc = Ahi*Bhi + Ahi*Blo + Alo*Bhi  (fp32 accumulate; lo*lo dropped ~2^-16).
// BM=128, BN=128, BK=16; 256 threads, warp tile 32x64.
// 3-stage cp.async pipeline (48 KB smem), grid: n fastest for A-tile L2 reuse.
// ---------------------------------------------------------------------------
__device__ __forceinline__ void cp16(void* dst, const void* src) {
    const uint32_t d = (uint32_t)__cvta_generic_to_shared(dst);
    asm volatile("cp.async.cg.shared.global [%0], [%1], 16;\n" :: "r"(d), "l"(src));
}
__device__ __forceinline__ void ldsm4(uint32_t* r, const __nv_bfloat16* p) {
    const uint32_t a = (uint32_t)__cvta_generic_to_shared(p);
    asm volatile("ldmatrix.sync.aligned.m8n8.x4.shared.b16 {%0,%1,%2,%3}, [%4];"
                 : "=r"(r[0]), "=r"(r[1]), "=r"(r[2]), "=r"(r[3]) : "r"(a));
}
__device__ __forceinline__ void mma16816(float* c, const uint32_t* a, uint32_t b0, uint32_t b1) {
    asm volatile("mma.sync.aligned.m16n8k16.row.col.f32.bf16.bf16.f32 "
                 "{%0,%1,%2,%3}, {%4,%5,%6,%7}, {%8,%9}, {%0,%1,%2,%3};"
                 : "+f"(c[0]), "+f"(c[1]), "+f"(c[2]), "+f"(c[3])
                 : "r"(a[0]), "r"(a[1]), "r"(a[2]), "r"(a[3]), "r"(b0), "r"(b1));
}

#define NIT (K_DIM / 16)   // 134

__global__ __launch_bounds__(256, 1) void gemm_kernel(
    const float* __restrict__ b_ih,
    const float* __restrict__ b_hh)
{
    __shared__ __align__(128) __nv_bfloat16 sA[3][2][128 * 16];
    __shared__ __align__(128) __nv_bfloat16 sB[3][2][128 * 16];

    const int tid = threadIdx.x;
    const int bn = blockIdx.x * 128;   // n fastest -> A-tile L2 reuse
    const int bm = blockIdx.y * 128;

    const int prow = tid >> 1;
    const int pch  = tid & 1;
    const int psc  = pch ^ ((prow >> 2) & 1);
    const int psoff = prow * 16 + psc * 8;
    const size_t aoff = (size_t)(bm + prow) * K_DIM + pch * 8;
    const size_t boff = (size_t)(bn + prow) * K_DIM + pch * 8;

    const int lane = tid & 31;
    const int warp = tid >> 5;
    const int wm = warp >> 1;
    const int wn = warp & 1;
    int aoffs[2];
#pragma unroll
    for (int mf = 0; mf < 2; ++mf) {
        const int r = wm * 32 + mf * 16 + (lane & 15);
        const int c = lane >> 4;
        aoffs[mf] = r * 16 + (c ^ ((r >> 2) & 1)) * 8;
    }
    int boffs[4];
#pragma unroll
    for (int ng = 0; ng < 4; ++ng) {
        const int r = wn * 64 + ng * 16 + ((lane & 7) | ((lane >> 4) << 3));
        const int c = (lane >> 3) & 1;
        boffs[ng] = r * 16 + (c ^ ((r >> 2) & 1)) * 8;
    }

    float acc[2][8][4];
#pragma unroll
    for (int mf = 0; mf < 2; ++mf)
#pragma unroll
        for (int n8 = 0; n8 < 8; ++n8)
#pragma unroll
            for (int q = 0; q < 4; ++q) acc[mf][n8][q] = 0.f;

#pragma unroll
    for (int p = 0; p < 2; ++p) {
        const size_t kk = (size_t)p * 16;
        cp16(&sA[p][0][psoff], g_Ahi + aoff + kk);
        cp16(&sA[p][1][psoff], g_Alo + aoff + kk);
        cp16(&sB[p][0][psoff], g_Bhi + boff + kk);
        cp16(&sB[p][1][psoff], g_Blo + boff + kk);
        asm volatile("cp.async.commit_group;\n" ::);
    }

    int st = 0;
    for (int it = 0; it < NIT; ++it) {
        asm volatile("cp.async.wait_group 1;\n" ::);
        __syncthreads();

        if (it + 2 < NIT) {
            const int ns = (st + 2 >= 3) ? st - 1 : st + 2;
            const size_t kk = (size_t)(it + 2) * 16;
            cp16(&sA[ns][0][psoff], g_Ahi + aoff + kk);
            cp16(&sA[ns][1][psoff], g_Alo + aoff + kk);
            cp16(&sB[ns][0][psoff], g_Bhi + boff + kk);
            cp16(&sB[ns][1][psoff], g_Blo + boff + kk);
        }
        asm volatile("cp.async.commit_group;\n" ::);

        uint32_t ahi[2][4], alo[2][4], bhi[4][4], blo[4][4];
#pragma unroll
        for (int mf = 0; mf < 2; ++mf) {
            ldsm4(ahi[mf], &sA[st][0][aoffs[mf]]);
            ldsm4(alo[mf], &sA[st][1][aoffs[mf]]);
        }
#pragma unroll
        for (int ng = 0; ng < 4; ++ng) {
            ldsm4(bhi[ng], &sB[st][0][boffs[ng]]);
            ldsm4(blo[ng], &sB[st][1][boffs[ng]]);
        }
#pragma unroll
        for (int mf = 0; mf < 2; ++mf)
#pragma unroll
            for (int ng = 0; ng < 4; ++ng)
#pragma unroll
                for (int h = 0; h < 2; ++h) {
                    float* c = acc[mf][ng * 2 + h];
                    mma16816(c, ahi[mf], bhi[ng][2 * h], bhi[ng][2 * h + 1]);
                    mma16816(c, ahi[mf], blo[ng][2 * h], blo[ng][2 * h + 1]);
                    mma16816(c, alo[mf], bhi[ng][2 * h], bhi[ng][2 * h + 1]);
                }
        __syncthreads();
        st = (st == 2) ? 0 : st + 1;
    }

    const int qr = lane >> 2;
    const int qc = (lane & 3) * 2;
#pragma unroll
    for (int mf = 0; mf < 2; ++mf) {
#pragma unroll
        for (int n8 = 0; n8 < 8; ++n8) {
            const int m0 = bm + wm * 32 + mf * 16 + qr;
            const int n0 = bn + wn * 64 + n8 * 8 + qc;
            const float bias0 = b_ih[n0] + b_hh[n0];
            const float bias1 = b_ih[n0 + 1] + b_hh[n0 + 1];
            const float* c = acc[mf][n8];
            g_xproj[(size_t)m0 * GATES + n0]           = c[0] + bias0;
            g_xproj[(size_t)m0 * GATES + n0 + 1]       = c[1] + bias1;
            g_xproj[(size_t)(m0 + 8) * GATES + n0]     = c[2] + bias0;
            g_xproj[(size_t)(m0 + 8) * GATES + n0 + 1] = c[3] + bias1;
        }
    }
}

// ---------------------------------------------------------------------------
// Kernel 3: LSTM recurrence (R6 version — known 198 us). 148 blocks:
// 104 x 3 seqs + 44 x 2 seqs. Plain C++ loads so ptxas can hoist/schedule;
// xproj for step s+1 prefetched during step s; __expf activations.
// ---------------------------------------------------------------------------
__device__ __forceinline__ float fsig(float x) {
    const float z = __expf(-fabsf(x));
    const float p = __fdividef(1.f, 1.f + z);
    return x >= 0.f ? p : 1.f - p;
}
__device__ __forceinline__ float ftanh_(float x) {
    const float t = __expf(-2.f * fabsf(x));
    const float r = __fdividef(1.f - t, 1.f + t);
    return x >= 0.f ? r : -r;
}

__global__ __launch_bounds__(512, 1) void lstm_kernel(
    const float* __restrict__ Whh,
    float* __restrict__ out)
{
    __shared__ float h_sh[3 * 128];
    __shared__ float gates_sh[3 * 512];

    const int tid = threadIdx.x;
    const int blk = blockIdx.x;
    int n0, ns;
    if (blk < 104) { n0 = 3 * blk; ns = 3; }
    else           { n0 = 312 + 2 * (blk - 104); ns = 2; }

    // Register-cache lower 64 recurrent weights of this gate row.
    float wreg[64];
    {
        const float4* wp = (const float4*)(Whh + tid * 128);
#pragma unroll
        for (int i = 0; i < 16; i++) {
            const float4 t = wp[i];
            wreg[i * 4 + 0] = t.x; wreg[i * 4 + 1] = t.y;
            wreg[i * 4 + 2] = t.z; wreg[i * 4 + 3] = t.w;
        }
    }
    const float* __restrict__ wgu = Whh + tid * 128 + 64;  // upper half (L1-resident)

    if (tid < 384) h_sh[tid] = 0.f;    // covers 3*128; seq 2 slot stays 0 for ns==2
    const int sq = tid >> 7;           // 0..3
    const int j  = tid & 127;
    const int active = (sq < ns);
    float creg = 0.f;
    const int n_pw = n0 + (active ? sq : 0);
    const int bb = n_pw / 25;
    const int vv = n_pw % 25;
    const long outbase = ((long)(bb * 128 + j) * 50) * 25 + vv;

    // prefetch step 0
    float xp0 = g_xproj[(size_t)((n0 + 0) * 50 + 0) * GATES + tid];
    float xp1 = g_xproj[(size_t)((n0 + 1) * 50 + 0) * GATES + tid];
    float xp2 = (ns == 3) ? g_xproj[(size_t)((n0 + 2) * 50 + 0) * GATES + tid] : 0.f;
    __syncthreads();

    for (int s = 0; s < NSEG; s++) {
        // issue prefetch for step s+1 (consumed next iteration)
        float nx0 = 0.f, nx1 = 0.f, nx2 = 0.f;
        if (s + 1 < NSEG) {
            nx0 = g_xproj[(size_t)((n0 + 0) * 50 + s + 1) * GATES + tid];
            nx1 = g_xproj[(size_t)((n0 + 1) * 50 + s + 1) * GATES + tid];
            if (ns == 3) nx2 = g_xproj[(size_t)((n0 + 2) * 50 + s + 1) * GATES + tid];
        }

        float acc0 = xp0, acc1 = xp1, acc2 = xp2;
        // lower 64 k: weights in registers (h for seq2 reads zeros when ns==2)
#pragma unroll
        for (int k = 0; k < 64; k += 4) {
            const float4 h0 = *(const float4*)&h_sh[0 * 128 + k];
            const float4 h1 = *(const float4*)&h_sh[1 * 128 + k];
            const float4 h2 = *(const float4*)&h_sh[2 * 128 + k];
            const float w0 = wreg[k], w1 = wreg[k + 1], w2 = wreg[k + 2], w3 = wreg[k + 3];
            acc0 += w0 * h0.x + w1 * h0.y + w2 * h0.z + w3 * h0.w;
            acc1 += w0 * h1.x + w1 * h1.y + w2 * h1.z + w3 * h1.w;
            acc2 += w0 * h2.x + w1 * h2.y + w2 * h2.z + w3 * h2.w;
        }
        // upper 64 k: weights from L1/L2
#pragma unroll
        for (int k = 0; k < 64; k += 4) {
            const float4 w4 = *(const float4*)&wgu[k];
            const float4 h0 = *(const float4*)&h_sh[0 * 128 + 64 + k];
            const float4 h1 = *(const float4*)&h_sh[1 * 128 + 64 + k];
            const float4 h2 = *(const float4*)&h_sh[2 * 128 + 64 + k];
            acc0 += w4.x * h0.x + w4.y * h0.y + w4.z * h0.z + w4.w * h0.w;
            acc1 += w4.x * h1.x + w4.y * h1.y + w4.z * h1.z + w4.w * h1.w;
            acc2 += w4.x * h2.x + w4.y * h2.y + w4.z * h2.z + w4.w * h2.w;
        }
        gates_sh[0 * 512 + tid] = acc0;
        gates_sh[1 * 512 + tid] = acc1;
        gates_sh[2 * 512 + tid] = acc2;
        __syncthreads();

        // pointwise: gates layout [i | f | g | o], 128 each
        if (active) {
            const float gi = gates_sh[sq * 512 + j];
            const float gf = gates_sh[sq * 512 + 128 + j];
            const float gg = gates_sh[sq * 512 + 256 + j];
            const float go = gates_sh[sq * 512 + 384 + j];
            creg = fsig(gf) * creg + fsig(gi) * ftanh_(gg);
            const float h = fsig(go) * ftanh_(creg);
            h_sh[sq * 128 + j] = h;
            out[outbase + (long)s * 25] = h;   // out[b, j, s, v]
        }
        __syncthreads();
        xp0 = nx0; xp1 = nx1; xp2 = nx2;
    }
}

// ---------------------------------------------------------------------------
extern "C" void kernel_launch(void* const* d_in, const int* in_sizes, int n_in,
                              void* d_out, int out_size) {
    const float* x    = (const float*)d_in[0];  // (16,64,200,25)
    const float* W_ih = (const float*)d_in[1];  // (512,2144)
    const float* W_hh = (const float*)d_in[2];  // (512,128)
    const float* b_ih = (const float*)d_in[3];  // (512)
    const float* b_hh = (const float*)d_in[4];  // (512)
    float* out = (float*)d_out;                 // (16,128,50,25)
    (void)in_sizes; (void)n_in; (void)out_size;

    dim3 gl(NSEG, 16, 5);
    logsig_kernel<<<gl, 256, 0, 0>>>(x);

    wconv_kernel<<<(GATES * K_DIM + 255) / 256, 256, 0, 0>>>(W_ih);

    dim3 gg(GATES / 128, M_PAD / 128);          // (4, 157): n fastest
    gemm_kernel<<<gg, 256, 0, 0>>>(b_ih, b_hh);

    lstm_kernel<<<148, 512, 0, 0>>>(W_hh, out);
}

// round 15
// speedup vs baseline: 1.5656x; 1.3668x over previous
#include <cuda_runtime.h>
#include <cuda_fp16.h>
#include <math.h>
#include <stdint.h>

#define K_DIM 2144     // 64 + 2016 + 64
#define M_ROWS 20000
#define M_PAD 20096    // 157 * 128
#define NSEG 50
#define GATES 512

// Scratch (device globals: allocation-free, zero-initialized .bss).
// Padded rows [20000, 20096) stay zero forever.
__device__ __half g_Ahi[(size_t)M_PAD * K_DIM];   // features hi (fp16)
__device__ __half g_Alo[(size_t)M_PAD * K_DIM];   // features lo (fp16): A = hi + lo (exact-ish)
__device__ __half g_B[(size_t)GATES * K_DIM];     // W_ih (fp16, single-rounded)
__device__ float g_xproj[(size_t)M_PAD * GATES];  // seq @ W_ih^T + b_ih + b_hh

__device__ __forceinline__ void split_fp16(float x, __half& hi, __half& lo) {
    hi = __float2half_rn(x);
    lo = __float2half_rn(x - __half2float(hi));
}

// ---------------------------------------------------------------------------
// Kernel 1: segment log-signature -> split-fp16 feature rows.
// grid (50, 16, 5): z splits the 25 v values into chunks of 5.
// ---------------------------------------------------------------------------
__global__ void logsig_kernel(const float* __restrict__ x) {
    const int s  = blockIdx.x;       // 0..49
    const int b  = blockIdx.y;       // 0..15
    const int v0 = blockIdx.z * 5;   // 0,5,10,15,20
    __shared__ float sa[64 * 5];
    __shared__ float sb[64 * 5];
    __shared__ float sc[64 * 5];
    const int tid = threadIdx.x;

    for (int item = tid; item < 64 * 5; item += 256) {
        const int c  = item / 5;
        const int dv = item % 5;
        const int v  = v0 + dv;
        const long base = ((long)(b * 64 + c) * 200 + 4 * s) * 25 + v;
        const float p0 = x[base];
        const float p1 = x[base + 25];
        const float p2 = x[base + 50];
        const float p3 = x[base + 75];
        sa[c * 5 + dv] = p1 - p0;
        sb[c * 5 + dv] = p2 - p1;
        sc[c * 5 + dv] = p3 - p2;
        const size_t m = (size_t)(b * 25 + v) * NSEG + s;
        split_fp16(p3 - p0, g_Ahi[m * K_DIM + c],        g_Alo[m * K_DIM + c]);
        split_fp16(p0,      g_Ahi[m * K_DIM + 2080 + c], g_Alo[m * K_DIM + 2080 + c]);
    }
    __syncthreads();

    // Triangular (i,j) indices for this thread's 8 strided k values (once).
    int ii[8], jj[8];
    {
        int i = 0, off = 0;  // row i starts at off = 63*i - i*(i-1)/2
        for (int u = 0; u < 8; ++u) {
            const int k = tid + (u << 8);
            if (k < 2016) {
                while (off + (63 - i) <= k) { off += 63 - i; ++i; }
                ii[u] = i; jj[u] = i + 1 + (k - off);
            } else { ii[u] = 0; jj[u] = 1; }
        }
    }

    for (int dv = 0; dv < 5; ++dv) {
        const int v = v0 + dv;
        const size_t m = (size_t)(b * 25 + v) * NSEG + s;
        __half* __restrict__ dh = g_Ahi + m * K_DIM + 64;
        __half* __restrict__ dl = g_Alo + m * K_DIM + 64;
#pragma unroll
        for (int u = 0; u < 8; ++u) {
            const int k = tid + (u << 8);
            if (k < 2016) {
                const int i = ii[u], j = jj[u];
                const float ai = sa[i * 5 + dv], aj = sa[j * 5 + dv];
                const float bi = sb[i * 5 + dv], bj = sb[j * 5 + dv];
                const float ci = sc[i * 5 + dv], cj = sc[j * 5 + dv];
                const float val = 0.5f * (ai * bj - aj * bi + (ai + bi) * cj - (aj + bj) * ci);
                split_fp16(val, dh[k], dl[k]);
            }
        }
    }
}

// ---------------------------------------------------------------------------
// Kernel 1b: convert W_ih to fp16 (single rounding; the only precision loss).
// ---------------------------------------------------------------------------
__global__ void wconv_kernel(const float* __restrict__ W) {
    const int idx = blockIdx.x * 256 + threadIdx.x;
    if (idx < GATES * K_DIM) {
        g_B[idx] = __float2half_rn(W[idx]);
    }
}

// ---------------------------------------------------------------------------
// Kernel 2: x_proj = seq @ W_ih^T + bias via 2-pass fp16 HMMA.
// acc = Ahi*B + Alo*B  (A exact as hi+lo; only B carries 2^-11 rounding).
// BM=128, BN=128, BK=16; 256 threads, warp tile 32x64; 3-stage cp.async
// (36 KB smem -> 2 CTAs/SM); grid n-fastest for A-tile L2 reuse.
// ---------------------------------------------------------------------------
__device__ __forceinline__ void cp16(void* dst, const void* src) {
    const uint32_t d = (uint32_t)__cvta_generic_to_shared(dst);
    asm volatile("cp.async.cg.shared.global [%0], [%1], 16;\n" :: "r"(d), "l"(src));
}
__device__ __forceinline__ void ldsm4(uint32_t* r, const __half* p) {
    const uint32_t a = (uint32_t)__cvta_generic_to_shared(p);
    asm volatile("ldmatrix.sync.aligned.m8n8.x4.shared.b16 {%0,%1,%2,%3}, [%4];"
                 : "=r"(r[0]), "=r"(r[1]), "=r"(r[2]), "=r"(r[3]) : "r"(a));
}
__device__ __forceinline__ void mma16816(float* c, const uint32_t* a, uint32_t b0, uint32_t b1) {
    asm volatile("mma.sync.aligned.m16n8k16.row.col.f32.f16.f16.f32 "
                 "{%0,%1,%2,%3}, {%4,%5,%6,%7}, {%8,%9}, {%0,%1,%2,%3};"
                 : "+f"(c[0]), "+f"(c[1]), "+f"(c[2]), "+f"(c[3])
                 : "r"(a[0]), "r"(a[1]), "r"(a[2]), "r"(a[3]), "r"(b0), "r"(b1));
}

#define NIT (K_DIM / 16)   // 134

__global__ __launch_bounds__(256, 2) void gemm_kernel(
    const float* __restrict__ b_ih,
    const float* __restrict__ b_hh)
{
    // [stage][hi/lo][128 rows x 16 cols] A, [stage][...] B. 36 KB total.
    __shared__ __align__(128) __half sA[3][2][128 * 16];
    __shared__ __align__(128) __half sB[3][128 * 16];

    const int tid = threadIdx.x;
    const int bn = blockIdx.x * 128;   // n fastest -> A-tile L2 reuse
    const int bm = blockIdx.y * 128;

    const int prow = tid >> 1;                 // 0..127
    const int pch  = tid & 1;                  // logical 16B chunk
    const int psc  = pch ^ ((prow >> 2) & 1);  // swizzled chunk
    const int psoff = prow * 16 + psc * 8;     // half elems
    const size_t aoff = (size_t)(bm + prow) * K_DIM + pch * 8;
    const size_t boff = (size_t)(bn + prow) * K_DIM + pch * 8;

    const int lane = tid & 31;
    const int warp = tid >> 5;
    const int wm = warp >> 1;                  // m: wm*32
    const int wn = warp & 1;                   // n: wn*64
    int aoffs[2];
#pragma unroll
    for (int mf = 0; mf < 2; ++mf) {
        const int r = wm * 32 + mf * 16 + (lane & 15);
        const int c = lane >> 4;
        aoffs[mf] = r * 16 + (c ^ ((r >> 2) & 1)) * 8;
    }
    int boffs[4];
#pragma unroll
    for (int ng = 0; ng < 4; ++ng) {
        const int r = wn * 64 + ng * 16 + ((lane & 7) | ((lane >> 4) << 3));
        const int c = (lane >> 3) & 1;
        boffs[ng] = r * 16 + (c ^ ((r >> 2) & 1)) * 8;
    }

    float acc[2][8][4];
#pragma unroll
    for (int mf = 0; mf < 2; ++mf)
#pragma unroll
        for (int n8 = 0; n8 < 8; ++n8)
#pragma unroll
            for (int q = 0; q < 4; ++q) acc[mf][n8][q] = 0.f;

#pragma unroll
    for (int p = 0; p < 2; ++p) {
        const size_t kk = (size_t)p * 16;
        cp16(&sA[p][0][psoff], g_Ahi + aoff + kk);
        cp16(&sA[p][1][psoff], g_Alo + aoff + kk);
        cp16(&sB[p][psoff],    g_B   + boff + kk);
        asm volatile("cp.async.commit_group;\n" ::);
    }

    int st = 0;
    for (int it = 0; it < NIT; ++it) {
        asm volatile("cp.async.wait_group 1;\n" ::);
        __syncthreads();

        if (it + 2 < NIT) {
            const int ns = (st + 2 >= 3) ? st - 1 : st + 2;
            const size_t kk = (size_t)(it + 2) * 16;
            cp16(&sA[ns][0][psoff], g_Ahi + aoff + kk);
            cp16(&sA[ns][1][psoff], g_Alo + aoff + kk);
            cp16(&sB[ns][psoff],    g_B   + boff + kk);
        }
        asm volatile("cp.async.commit_group;\n" ::);

        uint32_t ahi[2][4], alo[2][4], bb[4][4];
#pragma unroll
        for (int mf = 0; mf < 2; ++mf) {
            ldsm4(ahi[mf], &sA[st][0][aoffs[mf]]);
            ldsm4(alo[mf], &sA[st][1][aoffs[mf]]);
        }
#pragma unroll
        for (int ng = 0; ng < 4; ++ng) {
            ldsm4(bb[ng], &sB[st][boffs[ng]]);
        }
#pragma unroll
        for (int mf = 0; mf < 2; ++mf)
#pragma unroll
            for (int ng = 0; ng < 4; ++ng)
#pragma unroll
                for (int h = 0; h < 2; ++h) {
                    float* c = acc[mf][ng * 2 + h];
                    mma16816(c, ahi[mf], bb[ng][2 * h], bb[ng][2 * h + 1]);
                    mma16816(c, alo[mf], bb[ng][2 * h], bb[ng][2 * h + 1]);
                }
        __syncthreads();
        st = (st == 2) ? 0 : st + 1;
    }

    // epilogue: c-frag lane mapping (m = l/4 (+8), n = 2*(l%4) (+1))
    const int qr = lane >> 2;
    const int qc = (lane & 3) * 2;
#pragma unroll
    for (int mf = 0; mf < 2; ++mf) {
#pragma unroll
        for (int n8 = 0; n8 < 8; ++n8) {
            const int m0 = bm + wm * 32 + mf * 16 + qr;
            const int n0 = bn + wn * 64 + n8 * 8 + qc;
            const float bias0 = b_ih[n0] + b_hh[n0];
            const float bias1 = b_ih[n0 + 1] + b_hh[n0 + 1];
            const float* c = acc[mf][n8];
            g_xproj[(size_t)m0 * GATES + n0]           = c[0] + bias0;
            g_xproj[(size_t)m0 * GATES + n0 + 1]       = c[1] + bias1;
            g_xproj[(size_t)(m0 + 8) * GATES + n0]     = c[2] + bias0;
            g_xproj[(size_t)(m0 + 8) * GATES + n0 + 1] = c[3] + bias1;
        }
    }
}

// ---------------------------------------------------------------------------
// Kernel 3: LSTM recurrence (unchanged: 197 us known-good). 148 blocks:
// 104 x 3 seqs + 44 x 2 seqs; xproj prefetch; __expf activations.
// ---------------------------------------------------------------------------
__device__ __forceinline__ float fsig(float x) {
    const float z = __expf(-fabsf(x));
    const float p = __fdividef(1.f, 1.f + z);
    return x >= 0.f ? p : 1.f - p;
}
__device__ __forceinline__ float ftanh_(float x) {
    const float t = __expf(-2.f * fabsf(x));
    const float r = __fdividef(1.f - t, 1.f + t);
    return x >= 0.f ? r : -r;
}

__global__ __launch_bounds__(512, 1) void lstm_kernel(
    const float* __restrict__ Whh,
    float* __restrict__ out)
{
    __shared__ float h_sh[3 * 128];
    __shared__ float gates_sh[3 * 512];

    const int tid = threadIdx.x;
    const int blk = blockIdx.x;
    int n0, ns;
    if (blk < 104) { n0 = 3 * blk; ns = 3; }
    else           { n0 = 312 + 2 * (blk - 104); ns = 2; }

    float wreg[64];
    {
        const float4* wp = (const float4*)(Whh + tid * 128);
#pragma unroll
        for (int i = 0; i < 16; i++) {
            const float4 t = wp[i];
            wreg[i * 4 + 0] = t.x; wreg[i * 4 + 1] = t.y;
            wreg[i * 4 + 2] = t.z; wreg[i * 4 + 3] = t.w;
        }
    }
    const float* __restrict__ wgu = Whh + tid * 128 + 64;

    if (tid < 384) h_sh[tid] = 0.f;
    const int sq = tid >> 7;
    const int j  = tid & 127;
    const int active = (sq < ns);
    float creg = 0.f;
    const int n_pw = n0 + (active ? sq : 0);
    const int bb = n_pw / 25;
    const int vv = n_pw % 25;
    const long outbase = ((long)(bb * 128 + j) * 50) * 25 + vv;

    float xp0 = g_xproj[(size_t)((n0 + 0) * 50 + 0) * GATES + tid];
    float xp1 = g_xproj[(size_t)((n0 + 1) * 50 + 0) * GATES + tid];
    float xp2 = (ns == 3) ? g_xproj[(size_t)((n0 + 2) * 50 + 0) * GATES + tid] : 0.f;
    __syncthreads();

    for (int s = 0; s < NSEG; s++) {
        float nx0 = 0.f, nx1 = 0.f, nx2 = 0.f;
        if (s + 1 < NSEG) {
            nx0 = g_xproj[(size_t)((n0 + 0) * 50 + s + 1) * GATES + tid];
            nx1 = g_xproj[(size_t)((n0 + 1) * 50 + s + 1) * GATES + tid];
            if (ns == 3) nx2 = g_xproj[(size_t)((n0 + 2) * 50 + s + 1) * GATES + tid];
        }

        float acc0 = xp0, acc1 = xp1, acc2 = xp2;
#pragma unroll
        for (int k = 0; k < 64; k += 4) {
            const float4 h0 = *(const float4*)&h_sh[0 * 128 + k];
            const float4 h1 = *(const float4*)&h_sh[1 * 128 + k];
            const float4 h2 = *(const float4*)&h_sh[2 * 128 + k];
            const float w0 = wreg[k], w1 = wreg[k + 1], w2 = wreg[k + 2], w3 = wreg[k + 3];
            acc0 += w0 * h0.x + w1 * h0.y + w2 * h0.z + w3 * h0.w;
            acc1 += w0 * h1.x + w1 * h1.y + w2 * h1.z + w3 * h1.w;
            acc2 += w0 * h2.x + w1 * h2.y + w2 * h2.z + w3 * h2.w;
        }
#pragma unroll
        for (int k = 0; k < 64; k += 4) {
            const float4 w4 = *(const float4*)&wgu[k];
            const float4 h0 = *(const float4*)&h_sh[0 * 128 + 64 + k];
            const float4 h1 = *(const float4*)&h_sh[1 * 128 + 64 + k];
            const float4 h2 = *(const float4*)&h_sh[2 * 128 + 64 + k];
            acc0 += w4.x * h0.x + w4.y * h0.y + w4.z * h0.z + w4.w * h0.w;
            acc1 += w4.x * h1.x + w4.y * h1.y + w4.z * h1.z + w4.w * h1.w;
            acc2 += w4.x * h2.x + w4.y * h2.y + w4.z * h2.z + w4.w * h2.w;
        }
        gates_sh[0 * 512 + tid] = acc0;
        gates_sh[1 * 512 + tid] = acc1;
        gates_sh[2 * 512 + tid] = acc2;
        __syncthreads();

        if (active) {
            const float gi = gates_sh[sq * 512 + j];
            const float gf = gates_sh[sq * 512 + 128 + j];
            const float gg = gates_sh[sq * 512 + 256 + j];
            const float go = gates_sh[sq * 512 + 384 + j];
            creg = fsig(gf) * creg + fsig(gi) * ftanh_(gg);
            const float h = fsig(go) * ftanh_(creg);
            h_sh[sq * 128 + j] = h;
            out[outbase + (long)s * 25] = h;
        }
        __syncthreads();
        xp0 = nx0; xp1 = nx1; xp2 = nx2;
    }
}

// ---------------------------------------------------------------------------
extern "C" void kernel_launch(void* const* d_in, const int* in_sizes, int n_in,
                              void* d_out, int out_size) {
    const float* x    = (const float*)d_in[0];  // (16,64,200,25)
    const float* W_ih = (const float*)d_in[1];  // (512,2144)
    const float* W_hh = (const float*)d_in[2];  // (512,128)
    const float* b_ih = (const float*)d_in[3];  // (512)
    const float* b_hh = (const float*)d_in[4];  // (512)
    float* out = (float*)d_out;                 // (16,128,50,25)
    (void)in_sizes; (void)n_in; (void)out_size;

    dim3 gl(NSEG, 16, 5);
    logsig_kernel<<<gl, 256, 0, 0>>>(x);

    wconv_kernel<<<(GATES * K_DIM + 255) / 256, 256, 0, 0>>>(W_ih);

    dim3 gg(GATES / 128, M_PAD / 128);          // (4, 157): n fastest
    gemm_kernel<<<gg, 256, 0, 0>>>(b_ih, b_hh);

    lstm_kernel<<<148, 512, 0, 0>>>(W_hh, out);
}

// round 16
// speedup vs baseline: 1.6450x; 1.0507x over previous
#include <cuda_runtime.h>
#include <cuda_fp16.h>
#include <math.h>
#include <stdint.h>

#define K_DIM 2144     // 64 + 2016 + 64
#define M_ROWS 20000
#define M_PAD 20096    // 157 * 128
#define NSEG 50
#define GATES 512

// Scratch (device globals: allocation-free, zero-initialized .bss).
__device__ __half g_Ahi[(size_t)M_PAD * K_DIM];   // features hi (fp16)
__device__ __half g_Alo[(size_t)M_PAD * K_DIM];   // features lo (fp16): A = hi + lo
__device__ __half g_B[(size_t)GATES * K_DIM];     // W_ih (fp16, single-rounded)
__device__ __half g_W16[GATES * 128];             // W_hh (fp16)
__device__ float g_xproj[(size_t)M_PAD * GATES];  // seq @ W_ih^T + b_ih + b_hh

__device__ __forceinline__ void split_fp16(float x, __half& hi, __half& lo) {
    hi = __float2half_rn(x);
    lo = __float2half_rn(x - __half2float(hi));
}

// ---------------------------------------------------------------------------
// Kernel 1: segment log-signature -> split-fp16 feature rows.
// ---------------------------------------------------------------------------
__global__ void logsig_kernel(const float* __restrict__ x) {
    const int s  = blockIdx.x;       // 0..49
    const int b  = blockIdx.y;       // 0..15
    const int v0 = blockIdx.z * 5;   // 0,5,10,15,20
    __shared__ float sa[64 * 5];
    __shared__ float sb[64 * 5];
    __shared__ float sc[64 * 5];
    const int tid = threadIdx.x;

    for (int item = tid; item < 64 * 5; item += 256) {
        const int c  = item / 5;
        const int dv = item % 5;
        const int v  = v0 + dv;
        const long base = ((long)(b * 64 + c) * 200 + 4 * s) * 25 + v;
        const float p0 = x[base];
        const float p1 = x[base + 25];
        const float p2 = x[base + 50];
        const float p3 = x[base + 75];
        sa[c * 5 + dv] = p1 - p0;
        sb[c * 5 + dv] = p2 - p1;
        sc[c * 5 + dv] = p3 - p2;
        const size_t m = (size_t)(b * 25 + v) * NSEG + s;
        split_fp16(p3 - p0, g_Ahi[m * K_DIM + c],        g_Alo[m * K_DIM + c]);
        split_fp16(p0,      g_Ahi[m * K_DIM + 2080 + c], g_Alo[m * K_DIM + 2080 + c]);
    }
    __syncthreads();

    int ii[8], jj[8];
    {
        int i = 0, off = 0;  // row i starts at off = 63*i - i*(i-1)/2
        for (int u = 0; u < 8; ++u) {
            const int k = tid + (u << 8);
            if (k < 2016) {
                while (off + (63 - i) <= k) { off += 63 - i; ++i; }
                ii[u] = i; jj[u] = i + 1 + (k - off);
            } else { ii[u] = 0; jj[u] = 1; }
        }
    }

    for (int dv = 0; dv < 5; ++dv) {
        const int v = v0 + dv;
        const size_t m = (size_t)(b * 25 + v) * NSEG + s;
        __half* __restrict__ dh = g_Ahi + m * K_DIM + 64;
        __half* __restrict__ dl = g_Alo + m * K_DIM + 64;
#pragma unroll
        for (int u = 0; u < 8; ++u) {
            const int k = tid + (u << 8);
            if (k < 2016) {
                const int i = ii[u], j = jj[u];
                const float ai = sa[i * 5 + dv], aj = sa[j * 5 + dv];
                const float bi = sb[i * 5 + dv], bj = sb[j * 5 + dv];
                const float ci = sc[i * 5 + dv], cj = sc[j * 5 + dv];
                const float val = 0.5f * (ai * bj - aj * bi + (ai + bi) * cj - (aj + bj) * ci);
                split_fp16(val, dh[k], dl[k]);
            }
        }
    }
}

// ---------------------------------------------------------------------------
// Kernel 1b: convert W_ih and W_hh to fp16.
// ---------------------------------------------------------------------------
__global__ void wconv_kernel(const float* __restrict__ W) {
    const int idx = blockIdx.x * 256 + threadIdx.x;
    if (idx < GATES * K_DIM) {
        g_B[idx] = __float2half_rn(W[idx]);
    }
}
__global__ void whhconv_kernel(const float* __restrict__ W) {
    const int idx = blockIdx.x * 256 + threadIdx.x;
    if (idx < GATES * 128) {
        g_W16[idx] = __float2half_rn(W[idx]);
    }
}

// ---------------------------------------------------------------------------
// Kernel 2: x_proj via 2-pass fp16 HMMA (unchanged from R14 — passing).
// ---------------------------------------------------------------------------
__device__ __forceinline__ void cp16(void* dst, const void* src) {
    const uint32_t d = (uint32_t)__cvta_generic_to_shared(dst);
    asm volatile("cp.async.cg.shared.global [%0], [%1], 16;\n" :: "r"(d), "l"(src));
}
__device__ __forceinline__ void ldsm4(uint32_t* r, const __half* p) {
    const uint32_t a = (uint32_t)__cvta_generic_to_shared(p);
    asm volatile("ldmatrix.sync.aligned.m8n8.x4.shared.b16 {%0,%1,%2,%3}, [%4];"
                 : "=r"(r[0]), "=r"(r[1]), "=r"(r[2]), "=r"(r[3]) : "r"(a));
}
__device__ __forceinline__ void mma16816(float* c, const uint32_t* a, uint32_t b0, uint32_t b1) {
    asm volatile("mma.sync.aligned.m16n8k16.row.col.f32.f16.f16.f32 "
                 "{%0,%1,%2,%3}, {%4,%5,%6,%7}, {%8,%9}, {%0,%1,%2,%3};"
                 : "+f"(c[0]), "+f"(c[1]), "+f"(c[2]), "+f"(c[3])
                 : "r"(a[0]), "r"(a[1]), "r"(a[2]), "r"(a[3]), "r"(b0), "r"(b1));
}

#define NIT (K_DIM / 16)   // 134

__global__ __launch_bounds__(256, 2) void gemm_kernel(
    const float* __restrict__ b_ih,
    const float* __restrict__ b_hh)
{
    __shared__ __align__(128) __half sA[3][2][128 * 16];
    __shared__ __align__(128) __half sB[3][128 * 16];

    const int tid = threadIdx.x;
    const int bn = blockIdx.x * 128;   // n fastest -> A-tile L2 reuse
    const int bm = blockIdx.y * 128;

    const int prow = tid >> 1;
    const int pch  = tid & 1;
    const int psc  = pch ^ ((prow >> 2) & 1);
    const int psoff = prow * 16 + psc * 8;
    const size_t aoff = (size_t)(bm + prow) * K_DIM + pch * 8;
    const size_t boff = (size_t)(bn + prow) * K_DIM + pch * 8;

    const int lane = tid & 31;
    const int warp = tid >> 5;
    const int wm = warp >> 1;
    const int wn = warp & 1;
    int aoffs[2];
#pragma unroll
    for (int mf = 0; mf < 2; ++mf) {
        const int r = wm * 32 + mf * 16 + (lane & 15);
        const int c = lane >> 4;
        aoffs[mf] = r * 16 + (c ^ ((r >> 2) & 1)) * 8;
    }
    int boffs[4];
#pragma unroll
    for (int ng = 0; ng < 4; ++ng) {
        const int r = wn * 64 + ng * 16 + ((lane & 7) | ((lane >> 4) << 3));
        const int c = (lane >> 3) & 1;
        boffs[ng] = r * 16 + (c ^ ((r >> 2) & 1)) * 8;
    }

    float acc[2][8][4];
#pragma unroll
    for (int mf = 0; mf < 2; ++mf)
#pragma unroll
        for (int n8 = 0; n8 < 8; ++n8)
#pragma unroll
            for (int q = 0; q < 4; ++q) acc[mf][n8][q] = 0.f;

#pragma unroll
    for (int p = 0; p < 2; ++p) {
        const size_t kk = (size_t)p * 16;
        cp16(&sA[p][0][psoff], g_Ahi + aoff + kk);
        cp16(&sA[p][1][psoff], g_Alo + aoff + kk);
        cp16(&sB[p][psoff],    g_B   + boff + kk);
        asm volatile("cp.async.commit_group;\n" ::);
    }

    int st = 0;
    for (int it = 0; it < NIT; ++it) {
        asm volatile("cp.async.wait_group 1;\n" ::);
        __syncthreads();

        if (it + 2 < NIT) {
            const int ns = (st + 2 >= 3) ? st - 1 : st + 2;
            const size_t kk = (size_t)(it + 2) * 16;
            cp16(&sA[ns][0][psoff], g_Ahi + aoff + kk);
            cp16(&sA[ns][1][psoff], g_Alo + aoff + kk);
            cp16(&sB[ns][psoff],    g_B   + boff + kk);
        }
        asm volatile("cp.async.commit_group;\n" ::);

        uint32_t ahi[2][4], alo[2][4], bb[4][4];
#pragma unroll
        for (int mf = 0; mf < 2; ++mf) {
            ldsm4(ahi[mf], &sA[st][0][aoffs[mf]]);
            ldsm4(alo[mf], &sA[st][1][aoffs[mf]]);
        }
#pragma unroll
        for (int ng = 0; ng < 4; ++ng) {
            ldsm4(bb[ng], &sB[st][boffs[ng]]);
        }
#pragma unroll
        for (int mf = 0; mf < 2; ++mf)
#pragma unroll
            for (int ng = 0; ng < 4; ++ng)
#pragma unroll
                for (int h = 0; h < 2; ++h) {
                    float* c = acc[mf][ng * 2 + h];
                    mma16816(c, ahi[mf], bb[ng][2 * h], bb[ng][2 * h + 1]);
                    mma16816(c, alo[mf], bb[ng][2 * h], bb[ng][2 * h + 1]);
                }
        __syncthreads();
        st = (st == 2) ? 0 : st + 1;
    }

    const int qr = lane >> 2;
    const int qc = (lane & 3) * 2;
#pragma unroll
    for (int mf = 0; mf < 2; ++mf) {
#pragma unroll
        for (int n8 = 0; n8 < 8; ++n8) {
            const int m0 = bm + wm * 32 + mf * 16 + qr;
            const int n0 = bn + wn * 64 + n8 * 8 + qc;
            const float bias0 = b_ih[n0] + b_hh[n0];
            const float bias1 = b_ih[n0 + 1] + b_hh[n0 + 1];
            const float* c = acc[mf][n8];
            g_xproj[(size_t)m0 * GATES + n0]           = c[0] + bias0;
            g_xproj[(size_t)m0 * GATES + n0 + 1]       = c[1] + bias1;
            g_xproj[(size_t)(m0 + 8) * GATES + n0]     = c[2] + bias0;
            g_xproj[(size_t)(m0 + 8) * GATES + n0 + 1] = c[3] + bias1;
        }
    }
}

// ---------------------------------------------------------------------------
// Kernel 3: tensor-core LSTM. 25 blocks x 16 seqs, 512 threads = 16 warps.
// Warp w computes gates n in [32w, 32w+32) for all 16 seqs via m16n8k16 HMMA:
//   - W_hh held as 32 B-fragments in registers (manual fragment-layout loads)
//   - h (fp16) read from padded smem as packed-pair A fragments
//   - acc initialized from g_xproj (C-fragment layout), fp32 throughout c-path
// Per step: mma phase -> STS gates -> barrier -> pointwise -> barrier.
// ---------------------------------------------------------------------------
__device__ __forceinline__ float fsig(float x) {
    const float z = __expf(-fabsf(x));
    const float p = __fdividef(1.f, 1.f + z);
    return x >= 0.f ? p : 1.f - p;
}
__device__ __forceinline__ float ftanh_(float x) {
    const float t = __expf(-2.f * fabsf(x));
    const float r = __fdividef(1.f - t, 1.f + t);
    return x >= 0.f ? r : -r;
}

#define HSTR 136   // h row stride (halves): 4*qrow+qc/2 -> conflict-free banks
#define GSTR 520   // gates row stride (floats): <=2-way conflicts

__global__ __launch_bounds__(512, 1) void lstm_kernel(float* __restrict__ out)
{
    __shared__ float gates_sh[16 * GSTR];   // 33.3 KB
    __shared__ __half h_sh[16 * HSTR];      // 4.4 KB

    const int tid  = threadIdx.x;
    const int lane = tid & 31;
    const int w    = tid >> 5;          // warp 0..15, gates n base = 32w
    const int seq0 = blockIdx.x * 16;

    const int qrow = lane >> 2;         // 0..7
    const int qc   = (lane & 3) * 2;

    // B fragments: reg0 = W[n][k0..k0+1], reg1 = W[n][k0+8..k0+9]
    uint32_t Bf[8][4][2];
#pragma unroll
    for (int kt = 0; kt < 8; ++kt)
#pragma unroll
        for (int nt = 0; nt < 4; ++nt) {
            const int n = w * 32 + nt * 8 + qrow;
            const int k = kt * 16 + qc;
            Bf[kt][nt][0] = *(const uint32_t*)&g_W16[n * 128 + k];
            Bf[kt][nt][1] = *(const uint32_t*)&g_W16[n * 128 + k + 8];
        }

    for (int i = tid; i < 16 * HSTR; i += 512) h_sh[i] = __ushort_as_half(0);

    // pointwise ownership: 4 units (m = sub+4u, j)
    const int sub = tid >> 7;
    const int j   = tid & 127;
    float creg[4] = {0.f, 0.f, 0.f, 0.f};
    int obase[4];
#pragma unroll
    for (int u = 0; u < 4; ++u) {
        const int m  = sub + 4 * u;
        const int sq = seq0 + m;
        obase[u] = ((sq / 25) * 128 + j) * 50 * 25 + (sq % 25);
    }

    const size_t xr0 = (size_t)(seq0 + qrow) * 50 * 512;
    const size_t xr1 = (size_t)(seq0 + qrow + 8) * 50 * 512;

    // prefetch xproj for s=0 (C-fragment layout: rows qrow, qrow+8; cols n,n+1)
    float xp[16];
#pragma unroll
    for (int nt = 0; nt < 4; ++nt) {
        const int n = w * 32 + nt * 8 + qc;
        const float2 p0 = *(const float2*)&g_xproj[xr0 + n];
        const float2 p1 = *(const float2*)&g_xproj[xr1 + n];
        xp[nt*4+0] = p0.x; xp[nt*4+1] = p0.y; xp[nt*4+2] = p1.x; xp[nt*4+3] = p1.y;
    }
    __syncthreads();

    for (int s = 0; s < NSEG; ++s) {
        float acc[4][4];
#pragma unroll
        for (int nt = 0; nt < 4; ++nt) {
            acc[nt][0] = xp[nt*4+0]; acc[nt][1] = xp[nt*4+1];
            acc[nt][2] = xp[nt*4+2]; acc[nt][3] = xp[nt*4+3];
        }
        // prefetch next step's xproj (xp regs free now; overlaps mma phase)
        if (s + 1 < NSEG) {
#pragma unroll
            for (int nt = 0; nt < 4; ++nt) {
                const int n = w * 32 + nt * 8 + qc;
                const float2 p0 = *(const float2*)&g_xproj[xr0 + (size_t)(s+1)*512 + n];
                const float2 p1 = *(const float2*)&g_xproj[xr1 + (size_t)(s+1)*512 + n];
                xp[nt*4+0] = p0.x; xp[nt*4+1] = p0.y; xp[nt*4+2] = p1.x; xp[nt*4+3] = p1.y;
            }
        }
        // gates += h @ W_hh^T : 8 k-tiles x 4 n-tiles
#pragma unroll
        for (int kt = 0; kt < 8; ++kt) {
            uint32_t Af[4];
            Af[0] = *(const uint32_t*)&h_sh[qrow * HSTR + kt * 16 + qc];
            Af[1] = *(const uint32_t*)&h_sh[(qrow + 8) * HSTR + kt * 16 + qc];
            Af[2] = *(const uint32_t*)&h_sh[qrow * HSTR + kt * 16 + qc + 8];
            Af[3] = *(const uint32_t*)&h_sh[(qrow + 8) * HSTR + kt * 16 + qc + 8];
#pragma unroll
            for (int nt = 0; nt < 4; ++nt)
                mma16816(acc[nt], Af, Bf[kt][nt][0], Bf[kt][nt][1]);
        }
        // dump gates to smem (C-fragment layout)
#pragma unroll
        for (int nt = 0; nt < 4; ++nt) {
            const int n = w * 32 + nt * 8 + qc;
            *(float2*)&gates_sh[qrow * GSTR + n]       = make_float2(acc[nt][0], acc[nt][1]);
            *(float2*)&gates_sh[(qrow + 8) * GSTR + n] = make_float2(acc[nt][2], acc[nt][3]);
        }
        __syncthreads();

        // pointwise: gates layout [i | f | g | o], 128 each
#pragma unroll
        for (int u = 0; u < 4; ++u) {
            const int m = sub + 4 * u;
            const float gi = gates_sh[m * GSTR + j];
            const float gf = gates_sh[m * GSTR + 128 + j];
            const float gg = gates_sh[m * GSTR + 256 + j];
            const float go = gates_sh[m * GSTR + 384 + j];
            creg[u] = fsig(gf) * creg[u] + fsig(gi) * ftanh_(gg);
            const float h = fsig(go) * ftanh_(creg[u]);
            h_sh[m * HSTR + j] = __float2half_rn(h);
            out[obase[u] + s * 25] = h;   // out[b, j, s, v]
        }
        __syncthreads();
    }
}

// ---------------------------------------------------------------------------
extern "C" void kernel_launch(void* const* d_in, const int* in_sizes, int n_in,
                              void* d_out, int out_size) {
    const float* x    = (const float*)d_in[0];  // (16,64,200,25)
    const float* W_ih = (const float*)d_in[1];  // (512,2144)
    const float* W_hh = (const float*)d_in[2];  // (512,128)
    const float* b_ih = (const float*)d_in[3];  // (512)
    const float* b_hh = (const float*)d_in[4];  // (512)
    float* out = (float*)d_out;                 // (16,128,50,25)
    (void)in_sizes; (void)n_in; (void)out_size;

    dim3 gl(NSEG, 16, 5);
    logsig_kernel<<<gl, 256, 0, 0>>>(x);

    wconv_kernel<<<(GATES * K_DIM + 255) / 256, 256, 0, 0>>>(W_ih);
    whhconv_kernel<<<(GATES * 128 + 255) / 256, 256, 0, 0>>>(W_hh);

    dim3 gg(GATES / 128, M_PAD / 128);          // (4, 157): n fastest
    gemm_kernel<<<gg, 256, 0, 0>>>(b_ih, b_hh);

    lstm_kernel<<<25, 512, 0, 0>>>(out);
}